// round 16
// baseline (speedup 1.0000x reference)
#include <cuda_runtime.h>
#include <cstdint>
#include <math.h>

// Problem constants
#define NN 50000
#define EE 800000
#define ET (EE + NN)      // edges + self loops
#define ND 128            // node dim
#define ED 16             // edge dim
#define OD 64             // out dim
#define HH 4              // heads
#define HC (HH * OD)      // 256

// ---------------- scratch (device globals; no allocation allowed) ----------
__device__ float    g_h[NN * HC];        // 51.2 MB : x @ W
__device__ float    g_asrc[NN * HH];
__device__ float    g_adst[NN * HH];
__device__ float    g_loop[NN * ED];     // mean incoming edge_attr per node
__device__ float    g_cnt[NN];
__device__ unsigned g_amax[NN * HH];     // encoded float max
__device__ float    g_denom[NN * HH];
__device__ float    g_alpha[ET * HH];    // logits -> exp values
__device__ float    g_accum[NN * OD];    // head-summed messages
__device__ float    g_Ve[ED * HH];       // W_e @ att_edge, folded

// ---------------- helpers ---------------------------------------------------
__device__ __forceinline__ unsigned enc_f(float f) {
    unsigned u = __float_as_uint(f);
    return (u & 0x80000000u) ? ~u : (u | 0x80000000u);
}
__device__ __forceinline__ float dec_f(unsigned e) {
    unsigned u = (e & 0x80000000u) ? (e & 0x7FFFFFFFu) : ~e;
    return __uint_as_float(u);
}
__device__ __forceinline__ void red_add_v4(float* p, float4 v) {
    asm volatile("red.global.add.v4.f32 [%0], {%1,%2,%3,%4};"
                 :: "l"(p), "f"(v.x), "f"(v.y), "f"(v.z), "f"(v.w) : "memory");
}
__device__ __forceinline__ void red_add_v2(float* p, float a, float b) {
    asm volatile("red.global.add.v2.f32 [%0], {%1,%2};"
                 :: "l"(p), "f"(a), "f"(b) : "memory");
}
__device__ __forceinline__ unsigned long long pack2(float v) {
    unsigned long long r;
    asm("mov.b64 %0, {%1, %1};" : "=l"(r) : "f"(v));
    return r;
}
__device__ __forceinline__ void fma2(unsigned long long& c, unsigned long long a,
                                     unsigned long long b) {
    asm("fma.rn.f32x2 %0, %1, %2, %0;" : "+l"(c) : "l"(a), "l"(b));
}

// ---------------- kernels ---------------------------------------------------

// zero / init all per-call accumulators (graph replays must start fresh)
__global__ void k_init() {
    int i = blockIdx.x * blockDim.x + threadIdx.x;
    int st = gridDim.x * blockDim.x;
    for (int t = i; t < NN * OD; t += st) g_accum[t] = 0.f;
    for (int t = i; t < NN * ED; t += st) g_loop[t] = 0.f;
    for (int t = i; t < NN * HH; t += st) { g_denom[t] = 0.f; g_amax[t] = 0x007FFFFFu; } // enc(-inf)
    for (int t = i; t < NN; t += st) g_cnt[t] = 0.f;
}

// Ve[k][h] = sum_c W_e[k, h*64+c] * att_edge[h, c]
__global__ void k_ve(const float* __restrict__ We, const float* __restrict__ ae) {
    int t = threadIdx.x;                 // 64 threads
    int k = t >> 2, h = t & 3;
    float s = 0.f;
    for (int c = 0; c < OD; c++) s += We[k * HC + h * OD + c] * ae[h * OD + c];
    g_Ve[k * HH + h] = s;
}

// h = x @ W  (M=50000, N=256, K=128)  fp32 via packed fma.rn.f32x2
__global__ __launch_bounds__(256, 1) void k_gemm(const float* __restrict__ x,
                                                 const float* __restrict__ W, int N) {
    __shared__ float Xs[128][32];   // 16 KB
    __shared__ float Ws[32][256];   // 32 KB  (total 48 KB exactly)
    int tid = threadIdx.x;
    int tx = tid & 15;              // col group: cols {j*32 + tx*2, +1}
    int ty = tid >> 4;              // row group: rows ty*8 .. ty*8+7
    int row0 = blockIdx.x * 128;

    unsigned long long acc[8][8];
#pragma unroll
    for (int r = 0; r < 8; r++)
#pragma unroll
        for (int j = 0; j < 8; j++) acc[r][j] = 0ull;

    for (int k0 = 0; k0 < ND; k0 += 32) {
#pragma unroll
        for (int p = 0; p < 4; p++) {               // X tile 128x32
            int r = (tid >> 3) + 32 * p;
            int c = (tid & 7) * 4;
            float4 v = make_float4(0.f, 0.f, 0.f, 0.f);
            int gr = row0 + r;
            if (gr < N) v = *(const float4*)(x + gr * ND + k0 + c);
            *(float4*)&Xs[r][c] = v;
        }
#pragma unroll
        for (int p = 0; p < 8; p++) {               // W tile 32x256
            int r = (tid >> 6) + 4 * p;
            int c = (tid & 63) * 4;
            *(float4*)&Ws[r][c] = *(const float4*)(W + (k0 + r) * HC + c);
        }
        __syncthreads();
#pragma unroll
        for (int kk = 0; kk < 32; kk++) {
            unsigned long long b[8];
#pragma unroll
            for (int j = 0; j < 8; j++)
                b[j] = *(const unsigned long long*)&Ws[kk][j * 32 + tx * 2];
#pragma unroll
            for (int r = 0; r < 8; r++) {
                unsigned long long a2 = pack2(Xs[ty * 8 + r][kk]);
#pragma unroll
                for (int j = 0; j < 8; j++) fma2(acc[r][j], a2, b[j]);
            }
        }
        __syncthreads();
    }
#pragma unroll
    for (int r = 0; r < 8; r++) {
        int gr = row0 + ty * 8 + r;
        if (gr < N) {
#pragma unroll
            for (int j = 0; j < 8; j++)
                *(unsigned long long*)(g_h + (size_t)gr * HC + j * 32 + tx * 2) = acc[r][j];
        }
    }
}

// a_src / a_dst : per (node, head) dot of h row with attention vectors
__global__ void k_attdot(const float* __restrict__ as, const float* __restrict__ ad, int N) {
    int t = blockIdx.x * blockDim.x + threadIdx.x;
    if (t >= N * HH) return;
    int n = t >> 2, hd = t & 3;
    const float* hp = g_h + (size_t)n * HC + hd * OD;
    const float* s1 = as + hd * OD;
    const float* s2 = ad + hd * OD;
    float d1 = 0.f, d2 = 0.f;
#pragma unroll
    for (int c = 0; c < OD; c += 4) {
        float4 hv = *(const float4*)(hp + c);
        float4 a1 = *(const float4*)(s1 + c);
        float4 a2 = *(const float4*)(s2 + c);
        d1 += hv.x * a1.x + hv.y * a1.y + hv.z * a1.z + hv.w * a1.w;
        d2 += hv.x * a2.x + hv.y * a2.y + hv.z * a2.z + hv.w * a2.w;
    }
    g_asrc[t] = d1;
    g_adst[t] = d2;
}

// incoming edge_attr sums + counts per node (for self-loop fill_value='mean')
__global__ void k_loopsum(const int* __restrict__ dst, const float* __restrict__ ea, int E) {
    int e = blockIdx.x * blockDim.x + threadIdx.x;
    if (e >= E) return;
    int d = dst[e];
    atomicAdd(&g_cnt[d], 1.0f);
    const float4* p = (const float4*)(ea + (size_t)e * ED);
    float* q = g_loop + (size_t)d * ED;
#pragma unroll
    for (int i = 0; i < 4; i++) red_add_v4(q + i * 4, p[i]);
}

__global__ void k_loopmean(int N) {
    int t = blockIdx.x * blockDim.x + threadIdx.x;
    if (t >= N * ED) return;
    int n = t >> 4;
    g_loop[t] *= 1.0f / fmaxf(g_cnt[n], 1.0f);
}

// logits (leaky relu) + segment max (encoded atomicMax)
__global__ void k_passA(const int* __restrict__ src, const int* __restrict__ dst,
                        const float* __restrict__ ea, int E, int Et) {
    int e = blockIdx.x * blockDim.x + threadIdx.x;
    if (e >= Et) return;
    int s, d;
    const float* ap;
    if (e < E) { s = src[e]; d = dst[e]; ap = ea + (size_t)e * ED; }
    else       { s = d = e - E; ap = g_loop + (size_t)(e - E) * ED; }

    float4 t1 = *(const float4*)(g_asrc + s * 4);
    float4 t2 = *(const float4*)(g_adst + d * 4);
    float a0 = t1.x + t2.x, a1 = t1.y + t2.y, a2 = t1.z + t2.z, a3 = t1.w + t2.w;
#pragma unroll
    for (int i = 0; i < 4; i++) {
        float4 ev = *(const float4*)(ap + i * 4);
        const float4* vp = (const float4*)(g_Ve + i * 16);
        float4 v0 = vp[0], v1 = vp[1], v2 = vp[2], v3 = vp[3];
        a0 += ev.x * v0.x + ev.y * v1.x + ev.z * v2.x + ev.w * v3.x;
        a1 += ev.x * v0.y + ev.y * v1.y + ev.z * v2.y + ev.w * v3.y;
        a2 += ev.x * v0.z + ev.y * v1.z + ev.z * v2.z + ev.w * v3.z;
        a3 += ev.x * v0.w + ev.y * v1.w + ev.z * v2.w + ev.w * v3.w;
    }
    a0 = a0 > 0.f ? a0 : 0.2f * a0;
    a1 = a1 > 0.f ? a1 : 0.2f * a1;
    a2 = a2 > 0.f ? a2 : 0.2f * a2;
    a3 = a3 > 0.f ? a3 : 0.2f * a3;
    *(float4*)(g_alpha + (size_t)e * 4) = make_float4(a0, a1, a2, a3);
    unsigned* am = g_amax + d * 4;
    atomicMax(am + 0, enc_f(a0));
    atomicMax(am + 1, enc_f(a1));
    atomicMax(am + 2, enc_f(a2));
    atomicMax(am + 3, enc_f(a3));
}

// exp(alpha - max) + segment sum
__global__ void k_passB(const int* __restrict__ dst, int E, int Et) {
    int e = blockIdx.x * blockDim.x + threadIdx.x;
    if (e >= Et) return;
    int d = (e < E) ? dst[e] : e - E;
    float4 al = *(const float4*)(g_alpha + (size_t)e * 4);
    uint4 mu = *(const uint4*)(g_amax + d * 4);
    float e0 = __expf(al.x - dec_f(mu.x));
    float e1 = __expf(al.y - dec_f(mu.y));
    float e2 = __expf(al.z - dec_f(mu.z));
    float e3 = __expf(al.w - dec_f(mu.w));
    *(float4*)(g_alpha + (size_t)e * 4) = make_float4(e0, e1, e2, e3);
    red_add_v4(g_denom + d * 4, make_float4(e0, e1, e2, e3));
}

// message aggregation, head-sum folded in: one warp per edge
__global__ void k_passC(const int* __restrict__ src, const int* __restrict__ dst,
                        int E, int Et) {
    int w = (blockIdx.x * blockDim.x + threadIdx.x) >> 5;
    int lane = threadIdx.x & 31;
    if (w >= Et) return;
    int s, d;
    if (w < E) { s = src[w]; d = dst[w]; } else { s = d = w - E; }
    float4 al = *(const float4*)(g_alpha + (size_t)w * 4);
    float4 dn = *(const float4*)(g_denom + d * 4);
    float att[4] = { al.x / (dn.x + 1e-16f), al.y / (dn.y + 1e-16f),
                     al.z / (dn.z + 1e-16f), al.w / (dn.w + 1e-16f) };
    const float* hp = g_h + (size_t)s * HC + lane * 2;
    float mx = 0.f, my = 0.f;
#pragma unroll
    for (int hd = 0; hd < 4; hd++) {
        float2 v = *(const float2*)(hp + hd * OD);
        mx += att[hd] * v.x;
        my += att[hd] * v.y;
    }
    red_add_v2(g_accum + (size_t)d * OD + lane * 2, mx, my);
}

// head mean + bias + layernorm + elu : one warp per node
__global__ void k_final(const float* __restrict__ bias, const float* __restrict__ gamma,
                        const float* __restrict__ beta, float* __restrict__ out, int N) {
    int w = (blockIdx.x * blockDim.x + threadIdx.x) >> 5;
    int lane = threadIdx.x & 31;
    if (w >= N) return;
    int c = lane * 2;
    float2 v = *(const float2*)(g_accum + (size_t)w * OD + c);
    float2 bv = *(const float2*)(bias + c);
    float vx = v.x * 0.25f + bv.x;
    float vy = v.y * 0.25f + bv.y;
    float s = vx + vy, sq = vx * vx + vy * vy;
#pragma unroll
    for (int o = 16; o; o >>= 1) {
        s += __shfl_xor_sync(0xffffffffu, s, o);
        sq += __shfl_xor_sync(0xffffffffu, sq, o);
    }
    float mean = s * (1.0f / 64.0f);
    float var = sq * (1.0f / 64.0f) - mean * mean;
    float inv = rsqrtf(var + 1e-5f);
    float2 gv = *(const float2*)(gamma + c);
    float2 be = *(const float2*)(beta + c);
    float o1 = (vx - mean) * inv * gv.x + be.x;
    float o2 = (vy - mean) * inv * gv.y + be.y;
    o1 = o1 > 0.f ? o1 : expm1f(o1);
    o2 = o2 > 0.f ? o2 : expm1f(o2);
    *(float2*)(out + (size_t)w * OD + c) = make_float2(o1, o2);
}

// ---------------- launch ----------------------------------------------------
extern "C" void kernel_launch(void* const* d_in, const int* in_sizes, int n_in,
                              void* d_out, int out_size) {
    const float* x         = (const float*)d_in[0];
    const int*   ei        = (const int*)d_in[1];
    // d_in[2] = batch (unused, single graph)
    const float* edge_attr = (const float*)d_in[3];
    const float* W         = (const float*)d_in[4];
    const float* att_src   = (const float*)d_in[5];
    const float* att_dst   = (const float*)d_in[6];
    const float* W_e       = (const float*)d_in[7];
    const float* att_edge  = (const float*)d_in[8];
    const float* bias      = (const float*)d_in[9];
    const float* gamma     = (const float*)d_in[10];
    const float* beta      = (const float*)d_in[11];
    float* out = (float*)d_out;

    const int N = NN, E = EE, Et = ET;
    const int* src = ei;
    const int* dst = ei + E;

    k_init<<<1024, 256>>>();
    k_ve<<<1, 64>>>(W_e, att_edge);
    k_gemm<<<(N + 127) / 128, 256>>>(x, W, N);
    k_attdot<<<(N * HH + 255) / 256, 256>>>(att_src, att_dst, N);
    k_loopsum<<<(E + 255) / 256, 256>>>(dst, edge_attr, E);
    k_loopmean<<<(N * ED + 255) / 256, 256>>>(N);
    k_passA<<<(Et + 255) / 256, 256>>>(src, dst, edge_attr, E, Et);
    k_passB<<<(Et + 255) / 256, 256>>>(dst, E, Et);
    k_passC<<<(Et + 7) / 8, 256>>>(src, dst, E, Et);
    k_final<<<(N + 7) / 8, 256>>>(bias, gamma, beta, out, N);
}

// round 17
// speedup vs baseline: 1.1607x; 1.1607x over previous
#include <cuda_runtime.h>
#include <cstdint>
#include <math.h>

// Problem constants
#define NN 50000
#define EE 800000
#define ET (EE + NN)      // edges + self loops
#define ND 128            // node dim
#define ED 16             // edge dim
#define OD 64             // out dim
#define HH 4              // heads
#define HC (HH * OD)      // 256

// ---------------- scratch (device globals; no allocation allowed) ----------
__device__ float    g_h[NN * HC];        // 51.2 MB : x @ W
__device__ float    g_asrc[NN * HH];
__device__ float    g_adst[NN * HH];
__device__ float    g_loop[NN * ED];     // mean incoming edge_attr per node
__device__ float    g_cnt[NN];
__device__ unsigned g_amax[NN * HH];     // encoded float max
__device__ float    g_denom[NN * HH];
__device__ float    g_alpha[ET * HH];    // logits -> exp values
__device__ float    g_accum[NN * OD];    // head-summed messages
__device__ float    g_Ve[ED * HH];       // W_e @ att_edge, folded

// ---------------- helpers ---------------------------------------------------
__device__ __forceinline__ unsigned enc_f(float f) {
    unsigned u = __float_as_uint(f);
    return (u & 0x80000000u) ? ~u : (u | 0x80000000u);
}
__device__ __forceinline__ float dec_f(unsigned e) {
    unsigned u = (e & 0x80000000u) ? (e & 0x7FFFFFFFu) : ~e;
    return __uint_as_float(u);
}
__device__ __forceinline__ void red_add_v4(float* p, float4 v) {
    asm volatile("red.global.add.v4.f32 [%0], {%1,%2,%3,%4};"
                 :: "l"(p), "f"(v.x), "f"(v.y), "f"(v.z), "f"(v.w) : "memory");
}
__device__ __forceinline__ unsigned long long pack2(float v) {
    unsigned long long r;
    asm("mov.b64 %0, {%1, %1};" : "=l"(r) : "f"(v));
    return r;
}
__device__ __forceinline__ void fma2(unsigned long long& c, unsigned long long a,
                                     unsigned long long b) {
    asm("fma.rn.f32x2 %0, %1, %2, %0;" : "+l"(c) : "l"(a), "l"(b));
}

// ---------------- kernels ---------------------------------------------------

// zero / init all per-call accumulators (graph replays must start fresh)
__global__ void k_init() {
    int i = blockIdx.x * blockDim.x + threadIdx.x;
    int st = gridDim.x * blockDim.x;
    for (int t = i; t < NN * OD; t += st) g_accum[t] = 0.f;
    for (int t = i; t < NN * ED; t += st) g_loop[t] = 0.f;
    for (int t = i; t < NN * HH; t += st) { g_denom[t] = 0.f; g_amax[t] = 0x007FFFFFu; } // enc(-inf)
    for (int t = i; t < NN; t += st) g_cnt[t] = 0.f;
}

// Ve[k][h] = sum_c W_e[k, h*64+c] * att_edge[h, c]
__global__ void k_ve(const float* __restrict__ We, const float* __restrict__ ae) {
    int t = threadIdx.x;                 // 64 threads
    int k = t >> 2, h = t & 3;
    float s = 0.f;
    for (int c = 0; c < OD; c++) s += We[k * HC + h * OD + c] * ae[h * OD + c];
    g_Ve[k * HH + h] = s;
}

// h = x @ W  (M=50000, N=256, K=128)  fp32 via packed fma.rn.f32x2
__global__ __launch_bounds__(256, 1) void k_gemm(const float* __restrict__ x,
                                                 const float* __restrict__ W, int N) {
    __shared__ float Xs[128][32];   // 16 KB
    __shared__ float Ws[32][256];   // 32 KB  (total 48 KB exactly)
    int tid = threadIdx.x;
    int tx = tid & 15;              // col group: cols {j*32 + tx*2, +1}
    int ty = tid >> 4;              // row group: rows ty*8 .. ty*8+7
    int row0 = blockIdx.x * 128;

    unsigned long long acc[8][8];
#pragma unroll
    for (int r = 0; r < 8; r++)
#pragma unroll
        for (int j = 0; j < 8; j++) acc[r][j] = 0ull;

    for (int k0 = 0; k0 < ND; k0 += 32) {
#pragma unroll
        for (int p = 0; p < 4; p++) {               // X tile 128x32
            int r = (tid >> 3) + 32 * p;
            int c = (tid & 7) * 4;
            float4 v = make_float4(0.f, 0.f, 0.f, 0.f);
            int gr = row0 + r;
            if (gr < N) v = *(const float4*)(x + gr * ND + k0 + c);
            *(float4*)&Xs[r][c] = v;
        }
#pragma unroll
        for (int p = 0; p < 8; p++) {               // W tile 32x256
            int r = (tid >> 6) + 4 * p;
            int c = (tid & 63) * 4;
            *(float4*)&Ws[r][c] = *(const float4*)(W + (k0 + r) * HC + c);
        }
        __syncthreads();
#pragma unroll
        for (int kk = 0; kk < 32; kk++) {
            unsigned long long b[8];
#pragma unroll
            for (int j = 0; j < 8; j++)
                b[j] = *(const unsigned long long*)&Ws[kk][j * 32 + tx * 2];
#pragma unroll
            for (int r = 0; r < 8; r++) {
                unsigned long long a2 = pack2(Xs[ty * 8 + r][kk]);
#pragma unroll
                for (int j = 0; j < 8; j++) fma2(acc[r][j], a2, b[j]);
            }
        }
        __syncthreads();
    }
#pragma unroll
    for (int r = 0; r < 8; r++) {
        int gr = row0 + ty * 8 + r;
        if (gr < N) {
#pragma unroll
            for (int j = 0; j < 8; j++)
                *(unsigned long long*)(g_h + (size_t)gr * HC + j * 32 + tx * 2) = acc[r][j];
        }
    }
}

// a_src / a_dst : per (node, head) dot; att vectors staged in shared once per block
__global__ __launch_bounds__(256) void k_attdot(const float* __restrict__ as,
                                                const float* __restrict__ ad, int N) {
    __shared__ float4 s1[64], s2[64];    // att_src / att_dst  (256 floats each)
    int t = threadIdx.x;
    if (t < 64)        s1[t]       = ((const float4*)as)[t];
    else if (t < 128)  s2[t - 64]  = ((const float4*)ad)[t - 64];
    __syncthreads();

    int idx = blockIdx.x * 256 + t;
    if (idx >= N * HH) return;
    int n = idx >> 2, hd = idx & 3;
    const float4* hp = (const float4*)(g_h + (size_t)n * HC + hd * OD);
    float d1 = 0.f, d2 = 0.f;
#pragma unroll
    for (int c = 0; c < 16; c++) {
        float4 hv = hp[c];
        float4 a1 = s1[hd * 16 + c];
        float4 a2 = s2[hd * 16 + c];
        d1 += hv.x * a1.x + hv.y * a1.y + hv.z * a1.z + hv.w * a1.w;
        d2 += hv.x * a2.x + hv.y * a2.y + hv.z * a2.z + hv.w * a2.w;
    }
    g_asrc[idx] = d1;
    g_adst[idx] = d2;
}

// incoming edge_attr sums + counts per node (for self-loop fill_value='mean')
__global__ void k_loopsum(const int* __restrict__ dst, const float* __restrict__ ea, int E) {
    int e = blockIdx.x * blockDim.x + threadIdx.x;
    if (e >= E) return;
    int d = dst[e];
    atomicAdd(&g_cnt[d], 1.0f);
    const float4* p = (const float4*)(ea + (size_t)e * ED);
    float* q = g_loop + (size_t)d * ED;
#pragma unroll
    for (int i = 0; i < 4; i++) red_add_v4(q + i * 4, p[i]);
}

__global__ void k_loopmean(int N) {
    int t = blockIdx.x * blockDim.x + threadIdx.x;
    if (t >= N * ED) return;
    int n = t >> 4;
    g_loop[t] *= 1.0f / fmaxf(g_cnt[n], 1.0f);
}

// logits (leaky relu) + segment max (encoded atomicMax)
__global__ void k_passA(const int* __restrict__ src, const int* __restrict__ dst,
                        const float* __restrict__ ea, int E, int Et) {
    int e = blockIdx.x * blockDim.x + threadIdx.x;
    if (e >= Et) return;
    int s, d;
    const float* ap;
    if (e < E) { s = src[e]; d = dst[e]; ap = ea + (size_t)e * ED; }
    else       { s = d = e - E; ap = g_loop + (size_t)(e - E) * ED; }

    float4 t1 = *(const float4*)(g_asrc + s * 4);
    float4 t2 = *(const float4*)(g_adst + d * 4);
    float a0 = t1.x + t2.x, a1 = t1.y + t2.y, a2 = t1.z + t2.z, a3 = t1.w + t2.w;
#pragma unroll
    for (int i = 0; i < 4; i++) {
        float4 ev = *(const float4*)(ap + i * 4);
        const float4* vp = (const float4*)(g_Ve + i * 16);
        float4 v0 = vp[0], v1 = vp[1], v2 = vp[2], v3 = vp[3];
        a0 += ev.x * v0.x + ev.y * v1.x + ev.z * v2.x + ev.w * v3.x;
        a1 += ev.x * v0.y + ev.y * v1.y + ev.z * v2.y + ev.w * v3.y;
        a2 += ev.x * v0.z + ev.y * v1.z + ev.z * v2.z + ev.w * v3.z;
        a3 += ev.x * v0.w + ev.y * v1.w + ev.z * v2.w + ev.w * v3.w;
    }
    a0 = a0 > 0.f ? a0 : 0.2f * a0;
    a1 = a1 > 0.f ? a1 : 0.2f * a1;
    a2 = a2 > 0.f ? a2 : 0.2f * a2;
    a3 = a3 > 0.f ? a3 : 0.2f * a3;
    *(float4*)(g_alpha + (size_t)e * 4) = make_float4(a0, a1, a2, a3);
    unsigned* am = g_amax + d * 4;
    atomicMax(am + 0, enc_f(a0));
    atomicMax(am + 1, enc_f(a1));
    atomicMax(am + 2, enc_f(a2));
    atomicMax(am + 3, enc_f(a3));
}

// exp(alpha - max) + segment sum
__global__ void k_passB(const int* __restrict__ dst, int E, int Et) {
    int e = blockIdx.x * blockDim.x + threadIdx.x;
    if (e >= Et) return;
    int d = (e < E) ? dst[e] : e - E;
    float4 al = *(const float4*)(g_alpha + (size_t)e * 4);
    uint4 mu = *(const uint4*)(g_amax + d * 4);
    float e0 = __expf(al.x - dec_f(mu.x));
    float e1 = __expf(al.y - dec_f(mu.y));
    float e2 = __expf(al.z - dec_f(mu.z));
    float e3 = __expf(al.w - dec_f(mu.w));
    *(float4*)(g_alpha + (size_t)e * 4) = make_float4(e0, e1, e2, e3);
    red_add_v4(g_denom + d * 4, make_float4(e0, e1, e2, e3));
}

// message aggregation, head-sum folded in: one HALF-WARP per edge,
// lane covers 4 consecutive output cols -> 16 red.v4 per edge (was 32 red.v2)
__global__ __launch_bounds__(256) void k_passC(const int* __restrict__ src,
                                               const int* __restrict__ dst,
                                               int E, int Et) {
    int hw = (blockIdx.x * blockDim.x + threadIdx.x) >> 4;   // half-warp id = edge
    int lane = threadIdx.x & 15;
    if (hw >= Et) return;
    int s, d;
    if (hw < E) { s = src[hw]; d = dst[hw]; } else { s = d = hw - E; }
    float4 al = *(const float4*)(g_alpha + (size_t)hw * 4);
    float4 dn = *(const float4*)(g_denom + d * 4);
    float att0 = al.x / (dn.x + 1e-16f);
    float att1 = al.y / (dn.y + 1e-16f);
    float att2 = al.z / (dn.z + 1e-16f);
    float att3 = al.w / (dn.w + 1e-16f);
    const float4* hp = (const float4*)(g_h + (size_t)s * HC) + lane;  // lane*16B
    float4 v0 = hp[0];          // head 0, cols 4*lane..
    float4 v1 = hp[16];         // head 1
    float4 v2 = hp[32];         // head 2
    float4 v3 = hp[48];         // head 3
    float4 m;
    m.x = att0 * v0.x + att1 * v1.x + att2 * v2.x + att3 * v3.x;
    m.y = att0 * v0.y + att1 * v1.y + att2 * v2.y + att3 * v3.y;
    m.z = att0 * v0.z + att1 * v1.z + att2 * v2.z + att3 * v3.z;
    m.w = att0 * v0.w + att1 * v1.w + att2 * v2.w + att3 * v3.w;
    red_add_v4(g_accum + (size_t)d * OD + lane * 4, m);
}

// head mean + bias + layernorm + elu : one warp per node
__global__ void k_final(const float* __restrict__ bias, const float* __restrict__ gamma,
                        const float* __restrict__ beta, float* __restrict__ out, int N) {
    int w = (blockIdx.x * blockDim.x + threadIdx.x) >> 5;
    int lane = threadIdx.x & 31;
    if (w >= N) return;
    int c = lane * 2;
    float2 v = *(const float2*)(g_accum + (size_t)w * OD + c);
    float2 bv = *(const float2*)(bias + c);
    float vx = v.x * 0.25f + bv.x;
    float vy = v.y * 0.25f + bv.y;
    float s = vx + vy, sq = vx * vx + vy * vy;
#pragma unroll
    for (int o = 16; o; o >>= 1) {
        s += __shfl_xor_sync(0xffffffffu, s, o);
        sq += __shfl_xor_sync(0xffffffffu, sq, o);
    }
    float mean = s * (1.0f / 64.0f);
    float var = sq * (1.0f / 64.0f) - mean * mean;
    float inv = rsqrtf(var + 1e-5f);
    float2 gv = *(const float2*)(gamma + c);
    float2 be = *(const float2*)(beta + c);
    float o1 = (vx - mean) * inv * gv.x + be.x;
    float o2 = (vy - mean) * inv * gv.y + be.y;
    o1 = o1 > 0.f ? o1 : expm1f(o1);
    o2 = o2 > 0.f ? o2 : expm1f(o2);
    *(float2*)(out + (size_t)w * OD + c) = make_float2(o1, o2);
}

// ---------------- launch ----------------------------------------------------
extern "C" void kernel_launch(void* const* d_in, const int* in_sizes, int n_in,
                              void* d_out, int out_size) {
    const float* x         = (const float*)d_in[0];
    const int*   ei        = (const int*)d_in[1];
    // d_in[2] = batch (unused, single graph)
    const float* edge_attr = (const float*)d_in[3];
    const float* W         = (const float*)d_in[4];
    const float* att_src   = (const float*)d_in[5];
    const float* att_dst   = (const float*)d_in[6];
    const float* W_e       = (const float*)d_in[7];
    const float* att_edge  = (const float*)d_in[8];
    const float* bias      = (const float*)d_in[9];
    const float* gamma     = (const float*)d_in[10];
    const float* beta      = (const float*)d_in[11];
    float* out = (float*)d_out;

    const int N = NN, E = EE, Et = ET;
    const int* src = ei;
    const int* dst = ei + E;

    k_init<<<1024, 256>>>();
    k_ve<<<1, 64>>>(W_e, att_edge);
    k_gemm<<<(N + 127) / 128, 256>>>(x, W, N);
    k_attdot<<<(N * HH + 255) / 256, 256>>>(att_src, att_dst, N);
    k_loopsum<<<(E + 255) / 256, 256>>>(dst, edge_attr, E);
    k_loopmean<<<(N * ED + 255) / 256, 256>>>(N);
    k_passA<<<(Et + 255) / 256, 256>>>(src, dst, edge_attr, E, Et);
    k_passB<<<(Et + 255) / 256, 256>>>(dst, E, Et);
    k_passC<<<(Et * 16 + 255) / 256, 256>>>(src, dst, E, Et);
    k_final<<<(N + 7) / 8, 256>>>(bias, gamma, beta, out, N);
}